// round 1
// baseline (speedup 1.0000x reference)
#include <cuda_runtime.h>

// ---- problem constants ----
#define A_   3
#define H_   128
#define W_   128
#define C_   2
#define ATTRS 7
#define B_   64
#define T_   2
#define NCELLS (B_*A_*H_*W_)           // 3,145,728
#define CELLS_PER_CHUNK 1024
#define NCHUNKS (NCELLS/CELLS_PER_CHUNK)   // 3072
#define CHUNKS_PER_BATCH ((A_*H_*W_)/CELLS_PER_CHUNK)  // 48
#define THREADS 256
#define GRID    1024                   // 3 chunks per block, grid-stride
#define F4_PER_CHUNK (CELLS_PER_CHUNK*ATTRS/4)  // 1792 float4 = 28 KB

// ---- global scratch (no allocs allowed) ----
__device__ double g_acc[6];   // sx, sy, sw, sh, sconf, scls
__device__ float  g_tcx [B_][T_];
__device__ float  g_tcy [B_][T_];
__device__ float  g_tbw [B_][T_];
__device__ float  g_tbh [B_][T_];
__device__ float  g_tar [B_][T_];   // (bw-cx)*(bh-cy)  == area_t in reference
__device__ float  g_tcl [B_][T_];   // matched[...,5] value for this target
__device__ int    g_tkey[B_][T_];   // (anchor<<16)|(cellX<<8)|cellY

// ============================================================
// Kernel 1: tiny prep — zero accumulators + per-(b,t) target data
// ============================================================
__global__ void yolo_prep(const float* __restrict__ boxes,
                          const int*   __restrict__ labels,
                          const float* __restrict__ areas) {
    int tid = threadIdx.x;
    if (tid < 6) g_acc[tid] = 0.0;
    if (tid < B_ * T_) {
        int b = tid >> 1, t = tid & 1;
        const float* bx = boxes + (size_t)(b * T_ + t) * 4;
        float x1 = bx[0], y1 = bx[1], x2 = bx[2], y2 = bx[3];
        float cx = (x1 + x2) * 0.5f;
        float cy = (y1 + y2) * 0.5f;
        float bw = x2 - x1;
        float bh = y2 - y1;

        // best anchor: argmin |anchor_area - area| (first on ties)
        float ar = areas[b * T_ + t];
        float d0 = fabsf(10440.0f  - ar);   // 116*90
        float d1 = fabsf(30888.0f  - ar);   // 156*198
        float d2 = fabsf(121598.0f - ar);   // 373*326
        int   an = 0; float m = d0;
        if (d1 < m) { m = d1; an = 1; }
        if (d2 < m) { an = 2; }

        // cellX indexes H-dim, cellY indexes W-dim; stride = 8 (exact /8 == *0.125)
        int cX = (int)((bw - cx) * 0.125f);
        int cY = (int)((bh - cy) * 0.125f);

        int lab = labels[b * T_ + t];
        // full[...,5]: t==0 -> one_hot(lab,2)[1] = (lab==1)
        //              t==1 -> one_hot(lab-1,2)[1] = (lab==2)
        float tc = (t == 0) ? ((lab == 1) ? 1.0f : 0.0f)
                            : ((lab == 2) ? 1.0f : 0.0f);

        g_tcx [b][t] = cx;
        g_tcy [b][t] = cy;
        g_tbw [b][t] = bw;
        g_tbh [b][t] = bh;
        g_tar [b][t] = (bw - cx) * (bh - cy);
        g_tcl [b][t] = tc;
        g_tkey[b][t] = (an << 16) | (cX << 8) | cY;
    }
}

// ============================================================
// Kernel 2: main streaming kernel. SMEM-staged coalesced loads,
// 4 cells/thread, grid-stride over 3072 chunks of 1024 cells.
// ============================================================
__global__ __launch_bounds__(THREADS)
void yolo_main(const float4* __restrict__ q) {
    __shared__ float4 s[F4_PER_CHUNK];        // 28 KB
    __shared__ float  red[6][THREADS / 32];

    const int tid = threadIdx.x;

    float sx = 0.f, sy = 0.f, sw = 0.f, sh = 0.f, sc = 0.f, sl = 0.f;

    for (int chunk = blockIdx.x; chunk < NCHUNKS; chunk += gridDim.x) {
        __syncthreads();   // protect smem reuse across iterations

        // -- coalesced global -> smem (7 x float4 per thread) --
        size_t base = (size_t)chunk * F4_PER_CHUNK;
        #pragma unroll
        for (int m = 0; m < 7; m++)
            s[tid + m * THREADS] = q[base + tid + m * THREADS];

        // -- per-batch target constants (all cells of a chunk share b) --
        int b = chunk / CHUNKS_PER_BATCH;
        float tcx0 = g_tcx[b][0], tcx1 = g_tcx[b][1];
        float tcy0 = g_tcy[b][0], tcy1 = g_tcy[b][1];
        float tbw0 = g_tbw[b][0], tbw1 = g_tbw[b][1];
        float tbh0 = g_tbh[b][0], tbh1 = g_tbh[b][1];
        float tar0 = g_tar[b][0], tar1 = g_tar[b][1];
        float tcl0 = g_tcl[b][0], tcl1 = g_tcl[b][1];
        int   key0 = g_tkey[b][0], key1 = g_tkey[b][1];

        __syncthreads();

        // -- read my 4 cells (28 floats, conflict-free LDS.128) --
        float f[28];
        float4* fp = reinterpret_cast<float4*>(f);
        #pragma unroll
        for (int m = 0; m < 7; m++)
            fp[m] = s[tid * 7 + m];

        int n0 = chunk * CELLS_PER_CHUNK + tid * 4;
        #pragma unroll
        for (int k = 0; k < 4; k++) {
            int n = n0 + k;
            int j = n & (W_ - 1);
            int i = (n >> 7) & (H_ - 1);
            int a = (n >> 14) % A_;

            float xr   = f[7 * k + 0];
            float yr   = f[7 * k + 1];
            float w    = f[7 * k + 2];
            float h    = f[7 * k + 3];
            float conf = f[7 * k + 4];

            float fi = (float)i, fj = (float)j;
            float xp = xr - fi;
            float yp = yr - fj;
            float hw = 0.5f * w, hh = 0.5f * h;
            float px1 = xp - hw, px2 = xp + hw;
            float py1 = yp - hh, py2 = yp + hh;
            float area_p = (px2 - px1) * (py2 - py1);

            // suppress: max IoU over the 2 targets > 0.5 (division-free)
            float ix0 = fmaxf(fminf(px2, tbw0) - fmaxf(px1, tcx0), 0.0f);
            float iy0 = fmaxf(fminf(py2, tbh0) - fmaxf(py1, tcy0), 0.0f);
            float in0 = ix0 * iy0;
            bool sup  = in0 > 0.5f * (area_p + tar0 - in0 + 1e-16f);

            float ix1 = fmaxf(fminf(px2, tbw1) - fmaxf(px1, tcx1), 0.0f);
            float iy1 = fmaxf(fminf(py2, tbh1) - fmaxf(py1, tcy1), 0.0f);
            float in1 = ix1 * iy1;
            sup = sup || (in1 > 0.5f * (area_p + tar1 - in1 + 1e-16f));

            int key = (a << 16) | (i << 8) | j;
            if (key == key1 || key == key0) {
                // exact cell: target t=1 wins on overwrite
                bool  t1 = (key == key1);
                float cx = t1 ? tcx1 : tcx0;
                float cy = t1 ? tcy1 : tcy0;
                float bw = t1 ? tbw1 : tbw0;
                float bh = t1 ? tbh1 : tbh0;
                float tc = t1 ? tcl1 : tcl0;

                float dX = xp - (cx - fi);
                float dY = yp - (cy - fj);
                float dW = w - bw;
                float dH = h - bh;
                sx += dX * dX;  sy += dY * dY;
                sw += dW * dW;  sh += dH * dH;

                sc += -fmaxf(__logf(conf), -100.0f);

                float p0 = f[7 * k + 5];
                float p1 = f[7 * k + 6];
                if (tc != 0.0f) {
                    sl += -fmaxf(__logf(p0), -100.0f)
                        -  fmaxf(__logf(p1), -100.0f);
                } else {
                    sl += -fmaxf(__logf(1.0f - p0), -100.0f)
                        -  fmaxf(__logf(1.0f - p1), -100.0f);
                }
            } else if (!sup) {
                sc += -fmaxf(__logf(1.0f - conf), -100.0f);
            }
            // suppressed non-exact: conff=0,t=0 -> -log1p(0) = 0
        }
    }

    // -- reduction: warp shuffle -> block smem -> 6 double atomics --
    #pragma unroll
    for (int o = 16; o > 0; o >>= 1) {
        sx += __shfl_down_sync(0xffffffffu, sx, o);
        sy += __shfl_down_sync(0xffffffffu, sy, o);
        sw += __shfl_down_sync(0xffffffffu, sw, o);
        sh += __shfl_down_sync(0xffffffffu, sh, o);
        sc += __shfl_down_sync(0xffffffffu, sc, o);
        sl += __shfl_down_sync(0xffffffffu, sl, o);
    }
    int warp = tid >> 5, lane = tid & 31;
    if (lane == 0) {
        red[0][warp] = sx; red[1][warp] = sy; red[2][warp] = sw;
        red[3][warp] = sh; red[4][warp] = sc; red[5][warp] = sl;
    }
    __syncthreads();
    if (tid < 6) {
        float acc = 0.f;
        #pragma unroll
        for (int wv = 0; wv < THREADS / 32; wv++) acc += red[tid][wv];
        atomicAdd(&g_acc[tid], (double)acc);
    }
}

// ============================================================
// Kernel 3: finalize -> 7 outputs
// ============================================================
__global__ void yolo_fin(float* __restrict__ out) {
    if (threadIdx.x == 0) {
        double N = (double)NCELLS;
        double xL = g_acc[0] / N;
        double yL = g_acc[1] / N;
        double wL = g_acc[2] / N;
        double hL = g_acc[3] / N;
        double confL = g_acc[4] / N;
        double clsL  = g_acc[5] / (2.0 * N);
        double loss = 2.5 * (xL + yL) + 2.5 * (wL + hL) + confL + clsL;
        out[0] = (float)loss;
        out[1] = (float)xL;
        out[2] = (float)yL;
        out[3] = (float)wL;
        out[4] = (float)hL;
        out[5] = (float)confL;
        out[6] = (float)clsL;
    }
}

extern "C" void kernel_launch(void* const* d_in, const int* in_sizes, int n_in,
                              void* d_out, int out_size) {
    const float* output = (const float*)d_in[0];
    const float* boxes  = (const float*)d_in[1];
    const int*   labels = (const int*)  d_in[2];
    const float* areas  = (const float*)d_in[3];

    yolo_prep<<<1, 128>>>(boxes, labels, areas);
    yolo_main<<<GRID, THREADS>>>((const float4*)output);
    yolo_fin<<<1, 32>>>((float*)d_out);
}